// round 15
// baseline (speedup 1.0000x reference)
#include <cuda_runtime.h>
#include <cuda_fp16.h>
#include <cuda_bf16.h>

#define NODE_SIZE 100000
#define DIM 128

// Scratch:
//   g_zA4[n]: 64 B row, nibble d: int4( round( z[n,d] * 2^7 ) )  clamped +-7
//   g_zB4[n]: 64 B row, nibble d: int4( round( z[n,d]*w3b[d] * 2^10 ) ) clamped +-7
//   g_P[n] = sum_d relu(z[n,d]) * v[d]      (fp32, exact)
//   g_Q[n] = sum_d relu(z[n,d]) * v[128+d]
// logit(i,j) = P[i] + Q[j] + 2^-25 * nibble_dot(A4[i], B4[j])
__device__ unsigned char g_zA4[NODE_SIZE * 64];
__device__ unsigned char g_zB4[NODE_SIZE * 64];
__device__ float g_P[NODE_SIZE];
__device__ float g_Q[NODE_SIZE];

__device__ __forceinline__ int q4(float x) {
    int v = __float2int_rn(x);
    return max(-7, min(7, v));
}

// pack 4 consecutive dims into u16: byte0 = d0 | d1<<4, byte1 = d2 | d3<<4
__device__ __forceinline__ unsigned short pack_s4x4(float x, float y, float z, float w) {
    unsigned b0 = (unsigned)(q4(x) & 0xF) | ((unsigned)(q4(y) & 0xF) << 4);
    unsigned b1 = (unsigned)(q4(z) & 0xF) | ((unsigned)(q4(w) & 0xF) << 4);
    return (unsigned short)(b0 | (b1 << 8));
}

// ---- convert (UNCHANGED): 512 thr/block, 8 rows/warp/iter ----
__global__ __launch_bounds__(512, 1) void convert_kernel(const float* __restrict__ z,
                                                         const float* __restrict__ W2,
                                                         const float* __restrict__ W3) {
    __shared__ float sv[256];

    const int t    = threadIdx.x;
    const int lane = t & 31;

    // Phase A: 512 threads, 2 per dot: v[k] = sum_d W2[k,d]*W3[d]
    {
        int k    = t >> 1;
        int half = t & 1;
        const float4* w2r = reinterpret_cast<const float4*>(W2) + k * 32 + half * 16;
        const float4* w3r = reinterpret_cast<const float4*>(W3) + half * 16;
        float s = 0.f;
        #pragma unroll
        for (int i = 0; i < 16; ++i) {
            float4 r  = __ldg(w2r + i);
            float4 tt = __ldg(w3r + i);
            s = fmaf(r.x, tt.x, s);
            s = fmaf(r.y, tt.y, s);
            s = fmaf(r.z, tt.z, s);
            s = fmaf(r.w, tt.w, s);
        }
        s += __shfl_xor_sync(0xFFFFFFFFu, s, 1);
        if (half == 0) sv[k] = s;
    }
    __syncthreads();

    const int gwarp  = (blockIdx.x * blockDim.x + t) >> 5;
    const int nwarps = (gridDim.x * blockDim.x) >> 5;

    const float4 v1 = *reinterpret_cast<const float4*>(&sv[lane * 4]);
    const float4 v2 = *reinterpret_cast<const float4*>(&sv[128 + lane * 4]);
    float4 w3 = __ldg(reinterpret_cast<const float4*>(W3 + 128) + lane);
    const float sB = 1024.f;   // 2^10
    w3.x *= sB; w3.y *= sB; w3.z *= sB; w3.w *= sB;
    const float sA = 128.f;    // 2^7

    const float4* __restrict__ zrow = reinterpret_cast<const float4*>(z);
    unsigned short* __restrict__ A = reinterpret_cast<unsigned short*>(g_zA4);
    unsigned short* __restrict__ B = reinterpret_cast<unsigned short*>(g_zB4);

    for (int n = gwarp * 8; n + 7 < NODE_SIZE; n += nwarps * 8) {
        float4 f[8];
        #pragma unroll
        for (int i = 0; i < 8; ++i)
            f[i] = __ldg(zrow + (size_t)(n + i) * 32 + lane);

        #pragma unroll
        for (int i = 0; i < 8; ++i) {
            A[(n + i) * 32 + lane] = pack_s4x4(f[i].x * sA, f[i].y * sA,
                                               f[i].z * sA, f[i].w * sA);
            B[(n + i) * 32 + lane] = pack_s4x4(f[i].x * w3.x, f[i].y * w3.y,
                                               f[i].z * w3.z, f[i].w * w3.w);
        }

        float p[8], q[8];
        #pragma unroll
        for (int i = 0; i < 8; ++i) {
            float rx = fmaxf(f[i].x, 0.f), ry = fmaxf(f[i].y, 0.f);
            float rz = fmaxf(f[i].z, 0.f), rw = fmaxf(f[i].w, 0.f);
            float pp = rx * v1.x;
            pp = fmaf(ry, v1.y, pp);
            pp = fmaf(rz, v1.z, pp);
            pp = fmaf(rw, v1.w, pp);
            p[i] = pp;
            float qq = rx * v2.x;
            qq = fmaf(ry, v2.y, qq);
            qq = fmaf(rz, v2.z, qq);
            qq = fmaf(rw, v2.w, qq);
            q[i] = qq;
        }

        #pragma unroll
        for (int i = 0; i < 8; ++i) {
            p[i] += __shfl_xor_sync(0xFFFFFFFFu, p[i], 16);
            q[i] += __shfl_xor_sync(0xFFFFFFFFu, q[i], 16);
        }
        float m[8];
        #pragma unroll
        for (int i = 0; i < 8; ++i) m[i] = (lane & 16) ? q[i] : p[i];
        #pragma unroll
        for (int i = 0; i < 8; ++i) m[i] += __shfl_xor_sync(0xFFFFFFFFu, m[i], 8);
        float nn[4];
        #pragma unroll
        for (int i = 0; i < 4; ++i) nn[i] = (lane & 8) ? m[i + 4] : m[i];
        #pragma unroll
        for (int i = 0; i < 4; ++i) nn[i] += __shfl_xor_sync(0xFFFFFFFFu, nn[i], 4);
        float o0 = (lane & 4) ? nn[2] : nn[0];
        float o1 = (lane & 4) ? nn[3] : nn[1];
        o0 += __shfl_xor_sync(0xFFFFFFFFu, o0, 2);
        o1 += __shfl_xor_sync(0xFFFFFFFFu, o1, 2);
        float u = (lane & 2) ? o1 : o0;
        u += __shfl_xor_sync(0xFFFFFFFFu, u, 1);

        if (!(lane & 1)) {
            int row = (lane >> 1) & 7;
            if (lane & 16) g_Q[n + row] = u;
            else           g_P[n + row] = u;
        }
    }
}

// ---- main kernel: lane-owns-edge, 32 edges/warp-iter, idx prefetched ----
__device__ __forceinline__ int nib_dot(int2 A, int2 B) {
    int alo = (A.x << 4) & 0xF0F0F0F0, ahi = A.x & 0xF0F0F0F0;
    int blo = (B.x << 4) & 0xF0F0F0F0, bhi = B.x & 0xF0F0F0F0;
    int s = __dp4a(alo, blo, 0);
    s = __dp4a(ahi, bhi, s);
    alo = (A.y << 4) & 0xF0F0F0F0; ahi = A.y & 0xF0F0F0F0;
    blo = (B.y << 4) & 0xF0F0F0F0; bhi = B.y & 0xF0F0F0F0;
    s = __dp4a(alo, blo, s);
    return __dp4a(ahi, bhi, s);
}

__global__ __launch_bounds__(256, 3) void neumf_kernel(
    const int* __restrict__ e_true,
    const int* __restrict__ e_false,
    float* __restrict__ out,
    int E_true, int E_total)
{
    const int lane   = threadIdx.x & 31;
    const int grp    = lane >> 3;     // 4 groups of 8 lanes
    const int r      = lane & 7;      // position (= pass index this lane owns)
    const int warp   = (blockIdx.x * blockDim.x + threadIdx.x) >> 5;
    const int nwarps = (gridDim.x * blockDim.x) >> 5;
    const int gbase  = lane & ~7;     // first lane of this group

    const unsigned char* __restrict__ za = g_zA4;
    const unsigned char* __restrict__ zb = g_zB4;

    int e = warp * 32;
    const int stride = nwarps * 32;
    const int lanoff = 4 * r + grp;   // this lane's edge offset within the 32-block

    // Prologue: prefetch first iteration's indices
    int2 idL = make_int2(0, 0);
    if (e + 31 < E_total) {
        const int eL = e + lanoff;
        idL = __ldg(reinterpret_cast<const int2*>(
            eL < E_true ? e_true + 2 * eL : e_false + 2 * (eL - E_true)));
    }

    for (; e + 31 < E_total; e += stride) {
        // Prefetch NEXT iteration's indices (latency hidden under this iteration)
        int2 idNext = make_int2(0, 0);
        const int en = e + stride;
        if (en + 31 < E_total) {
            const int eN = en + lanoff;
            idNext = __ldg(reinterpret_cast<const int2*>(
                eN < E_true ? e_true + 2 * eN : e_false + 2 * (eN - E_true)));
        }

        // P/Q for this lane's edge — issued at iter top, consumed at the end
        const float pq = __ldg(g_P + idL.x) + __ldg(g_Q + idL.y);

        // Row gathers: pass p uses indices from lane gbase|p (idL already in regs)
        int2 A[8], B[8];
        #pragma unroll
        for (int p = 0; p < 8; ++p) {
            int ip = __shfl_sync(0xFFFFFFFFu, idL.x, gbase | p);
            int jp = __shfl_sync(0xFFFFFFFFu, idL.y, gbase | p);
            A[p] = __ldg(reinterpret_cast<const int2*>(za + ((size_t)(unsigned)ip << 6)) + r);
            B[p] = __ldg(reinterpret_cast<const int2*>(zb + ((size_t)(unsigned)jp << 6)) + r);
        }

        int s[8];
        #pragma unroll
        for (int p = 0; p < 8; ++p)
            s[p] = nib_dot(A[p], B[p]);

        // Select-tree reduce over the 8-lane group: 14 SHFL + 7 SEL.
        // Lands: lane r holds the complete group-sum of s[r].
        #pragma unroll
        for (int p = 0; p < 8; ++p)
            s[p] += __shfl_xor_sync(0xFFFFFFFFu, s[p], 4);
        int a0 = (lane & 4) ? s[4] : s[0];
        int a1 = (lane & 4) ? s[5] : s[1];
        int a2 = (lane & 4) ? s[6] : s[2];
        int a3 = (lane & 4) ? s[7] : s[3];
        a0 += __shfl_xor_sync(0xFFFFFFFFu, a0, 2);
        a1 += __shfl_xor_sync(0xFFFFFFFFu, a1, 2);
        a2 += __shfl_xor_sync(0xFFFFFFFFu, a2, 2);
        a3 += __shfl_xor_sync(0xFFFFFFFFu, a3, 2);
        int b0 = (lane & 2) ? a2 : a0;
        int b1 = (lane & 2) ? a3 : a1;
        b0 += __shfl_xor_sync(0xFFFFFFFFu, b0, 1);
        b1 += __shfl_xor_sync(0xFFFFFFFFu, b1, 1);
        int c = (lane & 1) ? b1 : b0;

        // Every lane finalizes and stores its own edge — fully parallel.
        float logit = fmaf((float)c, 0x1p-25f, pq);
        out[e + lanoff] = 1.f / (1.f + __expf(-logit));

        idL = idNext;
    }

    // Tail: one edge per warp; lanes 0..15 each load 4B of the 64B rows
    for (; e < E_total; ++e) {
        int2 ii = __ldg(reinterpret_cast<const int2*>(
             e < E_true ? e_true + 2 * e : e_false + 2 * (e - E_true)));
        int s = 0;
        if (lane < 16) {
            int a = __ldg(reinterpret_cast<const int*>(za + ((size_t)(unsigned)ii.x << 6)) + lane);
            int b = __ldg(reinterpret_cast<const int*>(zb + ((size_t)(unsigned)ii.y << 6)) + lane);
            int alo = (a << 4) & 0xF0F0F0F0, ahi = a & 0xF0F0F0F0;
            int blo = (b << 4) & 0xF0F0F0F0, bhi = b & 0xF0F0F0F0;
            s = __dp4a(alo, blo, 0);
            s = __dp4a(ahi, bhi, s);
        }
        float pq = __ldg(g_P + ii.x) + __ldg(g_Q + ii.y);
        #pragma unroll
        for (int off = 8; off; off >>= 1)
            s += __shfl_xor_sync(0xFFFFFFFFu, s, off);
        s += __shfl_xor_sync(0xFFFFFFFFu, s, 16);
        if (lane == 0)
            out[e] = 1.f / (1.f + __expf(-fmaf((float)s, 0x1p-25f, pq)));
    }
}

extern "C" void kernel_launch(void* const* d_in, const int* in_sizes, int n_in,
                              void* d_out, int out_size) {
    // metadata order: X, train_edges, train_false_edges, z, weight_two, weight_three
    const int*   e_true  = (const int*)  d_in[1];
    const int*   e_false = (const int*)  d_in[2];
    const float* z       = (const float*)d_in[3];
    const float* W2      = (const float*)d_in[4];
    const float* W3      = (const float*)d_in[5];
    float* out = (float*)d_out;

    const int E_true  = in_sizes[1] / 2;
    const int E_total = E_true + in_sizes[2] / 2;

    int sm_count = 148;
    cudaDeviceGetAttribute(&sm_count, cudaDevAttrMultiProcessorCount, 0);

    convert_kernel<<<sm_count, 512>>>(z, W2, W3);   // v (smem), A4, B4, P, Q

    int blocks_per_sm = 3;
    cudaOccupancyMaxActiveBlocksPerMultiprocessor(&blocks_per_sm, neumf_kernel, 256, 0);
    if (blocks_per_sm < 1) blocks_per_sm = 1;

    neumf_kernel<<<sm_count * blocks_per_sm, 256>>>(e_true, e_false, out,
                                                    E_true, E_total);
}

// round 16
// speedup vs baseline: 1.0231x; 1.0231x over previous
#include <cuda_runtime.h>
#include <cuda_fp16.h>
#include <cuda_bf16.h>

#define NODE_SIZE 100000
#define DIM 128

// Scratch:
//   g_zA4[n]: 64 B row, nibble d: int4( round( z[n,d] * 2^7 ) )  clamped +-7
//   g_zB4[n]: 64 B row, nibble d: int4( round( z[n,d]*w3b[d] * 2^10 ) ) clamped +-7
//   g_P[n] = sum_d relu(z[n,d]) * v[d]      (fp32, exact)
//   g_Q[n] = sum_d relu(z[n,d]) * v[128+d]
// logit(i,j) = P[i] + Q[j] + 2^-25 * nibble_dot(A4[i], B4[j])
__device__ unsigned char g_zA4[NODE_SIZE * 64];
__device__ unsigned char g_zB4[NODE_SIZE * 64];
__device__ float g_P[NODE_SIZE];
__device__ float g_Q[NODE_SIZE];

__device__ __forceinline__ int q4(float x) {
    int v = __float2int_rn(x);
    return max(-7, min(7, v));
}

// pack 4 consecutive dims into u16: byte0 = d0 | d1<<4, byte1 = d2 | d3<<4
__device__ __forceinline__ unsigned short pack_s4x4(float x, float y, float z, float w) {
    unsigned b0 = (unsigned)(q4(x) & 0xF) | ((unsigned)(q4(y) & 0xF) << 4);
    unsigned b1 = (unsigned)(q4(z) & 0xF) | ((unsigned)(q4(w) & 0xF) << 4);
    return (unsigned short)(b0 | (b1 << 8));
}

// ---- convert (UNCHANGED): 512 thr/block, 8 rows/warp/iter ----
__global__ __launch_bounds__(512, 1) void convert_kernel(const float* __restrict__ z,
                                                         const float* __restrict__ W2,
                                                         const float* __restrict__ W3) {
    __shared__ float sv[256];

    const int t    = threadIdx.x;
    const int lane = t & 31;

    // Phase A: 512 threads, 2 per dot: v[k] = sum_d W2[k,d]*W3[d]
    {
        int k    = t >> 1;
        int half = t & 1;
        const float4* w2r = reinterpret_cast<const float4*>(W2) + k * 32 + half * 16;
        const float4* w3r = reinterpret_cast<const float4*>(W3) + half * 16;
        float s = 0.f;
        #pragma unroll
        for (int i = 0; i < 16; ++i) {
            float4 r  = __ldg(w2r + i);
            float4 tt = __ldg(w3r + i);
            s = fmaf(r.x, tt.x, s);
            s = fmaf(r.y, tt.y, s);
            s = fmaf(r.z, tt.z, s);
            s = fmaf(r.w, tt.w, s);
        }
        s += __shfl_xor_sync(0xFFFFFFFFu, s, 1);
        if (half == 0) sv[k] = s;
    }
    __syncthreads();

    const int gwarp  = (blockIdx.x * blockDim.x + t) >> 5;
    const int nwarps = (gridDim.x * blockDim.x) >> 5;

    const float4 v1 = *reinterpret_cast<const float4*>(&sv[lane * 4]);
    const float4 v2 = *reinterpret_cast<const float4*>(&sv[128 + lane * 4]);
    float4 w3 = __ldg(reinterpret_cast<const float4*>(W3 + 128) + lane);
    const float sB = 1024.f;   // 2^10
    w3.x *= sB; w3.y *= sB; w3.z *= sB; w3.w *= sB;
    const float sA = 128.f;    // 2^7

    const float4* __restrict__ zrow = reinterpret_cast<const float4*>(z);
    unsigned short* __restrict__ A = reinterpret_cast<unsigned short*>(g_zA4);
    unsigned short* __restrict__ B = reinterpret_cast<unsigned short*>(g_zB4);

    for (int n = gwarp * 8; n + 7 < NODE_SIZE; n += nwarps * 8) {
        float4 f[8];
        #pragma unroll
        for (int i = 0; i < 8; ++i)
            f[i] = __ldg(zrow + (size_t)(n + i) * 32 + lane);

        #pragma unroll
        for (int i = 0; i < 8; ++i) {
            A[(n + i) * 32 + lane] = pack_s4x4(f[i].x * sA, f[i].y * sA,
                                               f[i].z * sA, f[i].w * sA);
            B[(n + i) * 32 + lane] = pack_s4x4(f[i].x * w3.x, f[i].y * w3.y,
                                               f[i].z * w3.z, f[i].w * w3.w);
        }

        float p[8], q[8];
        #pragma unroll
        for (int i = 0; i < 8; ++i) {
            float rx = fmaxf(f[i].x, 0.f), ry = fmaxf(f[i].y, 0.f);
            float rz = fmaxf(f[i].z, 0.f), rw = fmaxf(f[i].w, 0.f);
            float pp = rx * v1.x;
            pp = fmaf(ry, v1.y, pp);
            pp = fmaf(rz, v1.z, pp);
            pp = fmaf(rw, v1.w, pp);
            p[i] = pp;
            float qq = rx * v2.x;
            qq = fmaf(ry, v2.y, qq);
            qq = fmaf(rz, v2.z, qq);
            qq = fmaf(rw, v2.w, qq);
            q[i] = qq;
        }

        #pragma unroll
        for (int i = 0; i < 8; ++i) {
            p[i] += __shfl_xor_sync(0xFFFFFFFFu, p[i], 16);
            q[i] += __shfl_xor_sync(0xFFFFFFFFu, q[i], 16);
        }
        float m[8];
        #pragma unroll
        for (int i = 0; i < 8; ++i) m[i] = (lane & 16) ? q[i] : p[i];
        #pragma unroll
        for (int i = 0; i < 8; ++i) m[i] += __shfl_xor_sync(0xFFFFFFFFu, m[i], 8);
        float nn[4];
        #pragma unroll
        for (int i = 0; i < 4; ++i) nn[i] = (lane & 8) ? m[i + 4] : m[i];
        #pragma unroll
        for (int i = 0; i < 4; ++i) nn[i] += __shfl_xor_sync(0xFFFFFFFFu, nn[i], 4);
        float o0 = (lane & 4) ? nn[2] : nn[0];
        float o1 = (lane & 4) ? nn[3] : nn[1];
        o0 += __shfl_xor_sync(0xFFFFFFFFu, o0, 2);
        o1 += __shfl_xor_sync(0xFFFFFFFFu, o1, 2);
        float u = (lane & 2) ? o1 : o0;
        u += __shfl_xor_sync(0xFFFFFFFFu, u, 1);

        if (!(lane & 1)) {
            int row = (lane >> 1) & 7;
            if (lane & 16) g_Q[n + row] = u;
            else           g_P[n + row] = u;
        }
    }
}

// ---- main kernel: lane-owns-edge, 32 edges/warp-iter, two 4-pass gather waves ----
__device__ __forceinline__ int nib_dot(int2 A, int2 B) {
    int alo = (A.x << 4) & 0xF0F0F0F0, ahi = A.x & 0xF0F0F0F0;
    int blo = (B.x << 4) & 0xF0F0F0F0, bhi = B.x & 0xF0F0F0F0;
    int s = __dp4a(alo, blo, 0);
    s = __dp4a(ahi, bhi, s);
    alo = (A.y << 4) & 0xF0F0F0F0; ahi = A.y & 0xF0F0F0F0;
    blo = (B.y << 4) & 0xF0F0F0F0; bhi = B.y & 0xF0F0F0F0;
    s = __dp4a(alo, blo, s);
    return __dp4a(ahi, bhi, s);
}

__global__ __launch_bounds__(256, 4) void neumf_kernel(
    const int* __restrict__ e_true,
    const int* __restrict__ e_false,
    float* __restrict__ out,
    int E_true, int E_total)
{
    const int lane   = threadIdx.x & 31;
    const int grp    = lane >> 3;     // 4 groups of 8 lanes
    const int r      = lane & 7;      // position (= pass index this lane owns)
    const int warp   = (blockIdx.x * blockDim.x + threadIdx.x) >> 5;
    const int nwarps = (gridDim.x * blockDim.x) >> 5;
    const int gbase  = lane & ~7;     // first lane of this group

    const unsigned char* __restrict__ za = g_zA4;
    const unsigned char* __restrict__ zb = g_zB4;

    int e = warp * 32;
    const int stride = nwarps * 32;
    const int lanoff = 4 * r + grp;   // this lane's edge offset within the 32-block

    // Prologue: prefetch first iteration's indices
    int2 idL = make_int2(0, 0);
    if (e + 31 < E_total) {
        const int eL = e + lanoff;
        idL = __ldg(reinterpret_cast<const int2*>(
            eL < E_true ? e_true + 2 * eL : e_false + 2 * (eL - E_true)));
    }

    for (; e + 31 < E_total; e += stride) {
        // Prefetch NEXT iteration's indices (latency hidden under this iteration)
        int2 idNext = make_int2(0, 0);
        const int en = e + stride;
        if (en + 31 < E_total) {
            const int eN = en + lanoff;
            idNext = __ldg(reinterpret_cast<const int2*>(
                eN < E_true ? e_true + 2 * eN : e_false + 2 * (eN - E_true)));
        }

        // P/Q for this lane's edge — issued at iter top, consumed at the end
        const float pq = __ldg(g_P + idL.x) + __ldg(g_Q + idL.y);

        int s[8];
        int2 A[4], B[4];

        // Wave 0: passes 0..3
        #pragma unroll
        for (int p = 0; p < 4; ++p) {
            int ip = __shfl_sync(0xFFFFFFFFu, idL.x, gbase | p);
            int jp = __shfl_sync(0xFFFFFFFFu, idL.y, gbase | p);
            A[p] = __ldg(reinterpret_cast<const int2*>(za + ((size_t)(unsigned)ip << 6)) + r);
            B[p] = __ldg(reinterpret_cast<const int2*>(zb + ((size_t)(unsigned)jp << 6)) + r);
        }
        #pragma unroll
        for (int p = 0; p < 4; ++p)
            s[p] = nib_dot(A[p], B[p]);

        // Wave 1: passes 4..7 (reuse A/B buffers)
        #pragma unroll
        for (int p = 0; p < 4; ++p) {
            int ip = __shfl_sync(0xFFFFFFFFu, idL.x, gbase | (4 + p));
            int jp = __shfl_sync(0xFFFFFFFFu, idL.y, gbase | (4 + p));
            A[p] = __ldg(reinterpret_cast<const int2*>(za + ((size_t)(unsigned)ip << 6)) + r);
            B[p] = __ldg(reinterpret_cast<const int2*>(zb + ((size_t)(unsigned)jp << 6)) + r);
        }
        #pragma unroll
        for (int p = 0; p < 4; ++p)
            s[4 + p] = nib_dot(A[p], B[p]);

        // Select-tree reduce over the 8-lane group: 14 SHFL + 7 SEL.
        // Lands: lane r holds the complete group-sum of s[r].
        #pragma unroll
        for (int p = 0; p < 8; ++p)
            s[p] += __shfl_xor_sync(0xFFFFFFFFu, s[p], 4);
        int a0 = (lane & 4) ? s[4] : s[0];
        int a1 = (lane & 4) ? s[5] : s[1];
        int a2 = (lane & 4) ? s[6] : s[2];
        int a3 = (lane & 4) ? s[7] : s[3];
        a0 += __shfl_xor_sync(0xFFFFFFFFu, a0, 2);
        a1 += __shfl_xor_sync(0xFFFFFFFFu, a1, 2);
        a2 += __shfl_xor_sync(0xFFFFFFFFu, a2, 2);
        a3 += __shfl_xor_sync(0xFFFFFFFFu, a3, 2);
        int b0 = (lane & 2) ? a2 : a0;
        int b1 = (lane & 2) ? a3 : a1;
        b0 += __shfl_xor_sync(0xFFFFFFFFu, b0, 1);
        b1 += __shfl_xor_sync(0xFFFFFFFFu, b1, 1);
        int c = (lane & 1) ? b1 : b0;

        // Every lane finalizes and stores its own edge — fully parallel.
        float logit = fmaf((float)c, 0x1p-25f, pq);
        out[e + lanoff] = 1.f / (1.f + __expf(-logit));

        idL = idNext;
    }

    // Tail: one edge per warp; lanes 0..15 each load 4B of the 64B rows
    for (; e < E_total; ++e) {
        int2 ii = __ldg(reinterpret_cast<const int2*>(
             e < E_true ? e_true + 2 * e : e_false + 2 * (e - E_true)));
        int s = 0;
        if (lane < 16) {
            int a = __ldg(reinterpret_cast<const int*>(za + ((size_t)(unsigned)ii.x << 6)) + lane);
            int b = __ldg(reinterpret_cast<const int*>(zb + ((size_t)(unsigned)ii.y << 6)) + lane);
            int alo = (a << 4) & 0xF0F0F0F0, ahi = a & 0xF0F0F0F0;
            int blo = (b << 4) & 0xF0F0F0F0, bhi = b & 0xF0F0F0F0;
            s = __dp4a(alo, blo, 0);
            s = __dp4a(ahi, bhi, s);
        }
        float pq = __ldg(g_P + ii.x) + __ldg(g_Q + ii.y);
        #pragma unroll
        for (int off = 8; off; off >>= 1)
            s += __shfl_xor_sync(0xFFFFFFFFu, s, off);
        s += __shfl_xor_sync(0xFFFFFFFFu, s, 16);
        if (lane == 0)
            out[e] = 1.f / (1.f + __expf(-fmaf((float)s, 0x1p-25f, pq)));
    }
}

extern "C" void kernel_launch(void* const* d_in, const int* in_sizes, int n_in,
                              void* d_out, int out_size) {
    // metadata order: X, train_edges, train_false_edges, z, weight_two, weight_three
    const int*   e_true  = (const int*)  d_in[1];
    const int*   e_false = (const int*)  d_in[2];
    const float* z       = (const float*)d_in[3];
    const float* W2      = (const float*)d_in[4];
    const float* W3      = (const float*)d_in[5];
    float* out = (float*)d_out;

    const int E_true  = in_sizes[1] / 2;
    const int E_total = E_true + in_sizes[2] / 2;

    int sm_count = 148;
    cudaDeviceGetAttribute(&sm_count, cudaDevAttrMultiProcessorCount, 0);

    convert_kernel<<<sm_count, 512>>>(z, W2, W3);   // v (smem), A4, B4, P, Q

    int blocks_per_sm = 4;
    cudaOccupancyMaxActiveBlocksPerMultiprocessor(&blocks_per_sm, neumf_kernel, 256, 0);
    if (blocks_per_sm < 1) blocks_per_sm = 1;

    neumf_kernel<<<sm_count * blocks_per_sm, 256>>>(e_true, e_false, out,
                                                    E_true, E_total);
}